// round 6
// baseline (speedup 1.0000x reference)
#include <cuda_runtime.h>

// GlobalFilter: out = irfft2( rfft2(x, ortho) * W, ortho ) per (batch, channel)
// x: [512, 196, 384] f32 ; W: [14, 8, 384, 2] f32 ; out: [512, 196, 384] f32
//
// Round 5: weights staged GMEM->SMEM via cp.async at kernel start (zero
// register cost), overlapping Stage A; Stage B consumes them via LDS instead
// of ~250-cycle L2 loads inside its k-loop. Everything else as round 4.

#define NBATCH 512
#define HALF_W 8
#define NCH    384
#define CT_TILE 16
#define CTP     (CT_TILE + 1)   // padded smem channel dim for Fs
#define NTHREADS 128

#define C7_TAB {1.0f, 0.6234898018587336f, -0.2225209339563144f, -0.9009688679024191f, \
                -0.9009688679024191f, -0.2225209339563144f, 0.6234898018587336f}
#define S7_TAB {0.0f, 0.7818314824680298f, 0.9749279121818236f, 0.4338837391175581f, \
                -0.4338837391175581f, -0.9749279121818236f, -0.7818314824680298f}
#define CT14_TAB {1.0f, 0.9009688679024191f, 0.6234898018587336f, 0.2225209339563144f, \
                  -0.2225209339563144f, -0.6234898018587336f, -0.9009688679024191f}
#define ST14_TAB {0.0f, 0.4338837391175581f, 0.7818314824680298f, 0.9749279121818236f, \
                  0.9749279121818236f, 0.7818314824680298f, 0.4338837391175581f}

__device__ __forceinline__ float2 mk(float a, float b) { return make_float2(a, b); }

// Symmetric complex DFT-7 into registers. SGN=-1: e^{-2pi i kn/7}; +1: e^{+}.
template<int SGN>
__device__ __forceinline__ void cdft7(const float2 v[7], float2 X[7]) {
    const float c7[7] = C7_TAB;
    const float s7[7] = S7_TAB;
    float2 tp[4], tm[4];
#pragma unroll
    for (int n = 1; n <= 3; n++) {
        tp[n] = mk(v[n].x + v[7 - n].x, v[n].y + v[7 - n].y);
        tm[n] = mk(v[n].x - v[7 - n].x, v[n].y - v[7 - n].y);
    }
    X[0] = mk(v[0].x + tp[1].x + tp[2].x + tp[3].x,
              v[0].y + tp[1].y + tp[2].y + tp[3].y);
#pragma unroll
    for (int k = 1; k <= 3; k++) {
        float Ar = v[0].x, Ai = v[0].y, Br = 0.0f, Bi = 0.0f;
#pragma unroll
        for (int n = 1; n <= 3; n++) {
            const int j = (k * n) % 7;
            Ar = fmaf(tp[n].x, c7[j], Ar);
            Ai = fmaf(tp[n].y, c7[j], Ai);
            Br = fmaf(tm[n].x, s7[j], Br);
            Bi = fmaf(tm[n].y, s7[j], Bi);
        }
        if (SGN < 0) { X[k] = mk(Ar + Bi, Ai - Br); X[7 - k] = mk(Ar - Bi, Ai + Br); }
        else         { X[k] = mk(Ar - Bi, Ai + Br); X[7 - k] = mk(Ar + Bi, Ai - Br); }
    }
}

// Same DFT-7 but stores results straight to (strided) shared memory.
template<int SGN>
__device__ __forceinline__ void cdft7_store(const float2 v[7], float2* base, const int strideF2) {
    const float c7[7] = C7_TAB;
    const float s7[7] = S7_TAB;
    float2 tp[4], tm[4];
#pragma unroll
    for (int n = 1; n <= 3; n++) {
        tp[n] = mk(v[n].x + v[7 - n].x, v[n].y + v[7 - n].y);
        tm[n] = mk(v[n].x - v[7 - n].x, v[n].y - v[7 - n].y);
    }
    base[0] = mk(v[0].x + tp[1].x + tp[2].x + tp[3].x,
                 v[0].y + tp[1].y + tp[2].y + tp[3].y);
#pragma unroll
    for (int k = 1; k <= 3; k++) {
        float Ar = v[0].x, Ai = v[0].y, Br = 0.0f, Bi = 0.0f;
#pragma unroll
        for (int n = 1; n <= 3; n++) {
            const int j = (k * n) % 7;
            Ar = fmaf(tp[n].x, c7[j], Ar);
            Ai = fmaf(tp[n].y, c7[j], Ai);
            Br = fmaf(tm[n].x, s7[j], Br);
            Bi = fmaf(tm[n].y, s7[j], Bi);
        }
        if (SGN < 0) {
            base[k * strideF2]       = mk(Ar + Bi, Ai - Br);
            base[(7 - k) * strideF2] = mk(Ar - Bi, Ai + Br);
        } else {
            base[k * strideF2]       = mk(Ar - Bi, Ai + Br);
            base[(7 - k) * strideF2] = mk(Ar + Bi, Ai - Br);
        }
    }
}

// Real forward DFT-7: bins 0..3 (bin 0 purely real).
__device__ __forceinline__ void rdft7(const float r[7], float& R0, float2 R[4]) {
    const float c7[7] = C7_TAB;
    const float s7[7] = S7_TAB;
    float tp[4], tm[4];
#pragma unroll
    for (int n = 1; n <= 3; n++) { tp[n] = r[n] + r[7 - n]; tm[n] = r[n] - r[7 - n]; }
    R0 = r[0] + tp[1] + tp[2] + tp[3];
#pragma unroll
    for (int k = 1; k <= 3; k++) {
        float re = r[0], im = 0.0f;
#pragma unroll
        for (int n = 1; n <= 3; n++) {
            const int j = (k * n) % 7;
            re = fmaf(tp[n],  c7[j], re);
            im = fmaf(tm[n], -s7[j], im);
        }
        R[k] = mk(re, im);
    }
}

__global__ __launch_bounds__(NTHREADS, 7)
void gf_kernel(const float* __restrict__ x,
               const float* __restrict__ cw,
               float* __restrict__ out)
{
    __shared__ float2 Fs[14][HALF_W][CTP];       // ~15.2 KB
    __shared__ float2 Ws[14][HALF_W][CT_TILE];   // 14 KB, cp.async staged

    const int b   = blockIdx.x;
    const int c0  = blockIdx.y * CT_TILE;
    const int tid = threadIdx.x;

    // -- Kick off async weight staging: 14*8*16 float2 = 896 x 16B chunks --
    {
        const float2* wsrc = (const float2*)cw;   // [14*8][384] float2 rows
        unsigned dst_base = (unsigned)__cvta_generic_to_shared(&Ws[0][0][0]);
#pragma unroll
        for (int i = 0; i < 7; i++) {
            const int idx   = tid + i * NTHREADS;    // 0..895
            const int row   = idx >> 3;              // k1*8+k2, 0..111
            const int chunk = idx & 7;               // 16B chunk in row
            const float2* src = wsrc + (size_t)row * NCH + c0 + chunk * 2;
            unsigned dst = dst_base + (unsigned)(row * CT_TILE + chunk * 2) * 8u;
            asm volatile("cp.async.ca.shared.global [%0], [%1], 16;\n"
                         :: "r"(dst), "l"(src));
        }
        asm volatile("cp.async.commit_group;\n");
    }

    // ------- Stage A: row rfft-14 over n2, float2 channel pairs -------
    if (tid < 14 * (CT_TILE / 2)) {
        const float ct[7] = CT14_TAB;
        const float st[7] = ST14_TAB;
        const int cp = tid & (CT_TILE / 2 - 1);   // channel pair 0..7
        const int n1 = tid / (CT_TILE / 2);
        const float2* xrow =
            reinterpret_cast<const float2*>(x + ((size_t)(b * 196 + n1 * 14)) * NCH + c0) + cp;
        float2 in2[14];
#pragma unroll
        for (int n = 0; n < 14; n++) in2[n] = xrow[n * (NCH / 2)];

#pragma unroll
        for (int h = 0; h < 2; h++) {
            float ev[7], od[7];
#pragma unroll
            for (int n = 0; n < 7; n++) {
                ev[n] = h ? in2[2 * n].y     : in2[2 * n].x;
                od[n] = h ? in2[2 * n + 1].y : in2[2 * n + 1].x;
            }
            float E0, O0;
            float2 E[4], O[4];
            rdft7(ev, E0, E);
            rdft7(od, O0, O);

            const int c = 2 * cp + h;
            Fs[n1][0][c] = mk(E0 + O0, 0.0f);
            Fs[n1][7][c] = mk(E0 - O0, 0.0f);
#pragma unroll
            for (int k = 1; k <= 3; k++) {  // F[k] = E[k] + (c - i s) O[k]
                const float tr = fmaf(ct[k], O[k].x,  st[k] * O[k].y);
                const float ti = fmaf(ct[k], O[k].y, -st[k] * O[k].x);
                Fs[n1][k][c] = mk(E[k].x + tr, E[k].y + ti);
            }
#pragma unroll
            for (int k = 4; k <= 6; k++) {  // conj-symmetry of E,O
                const float orr = O[7 - k].x, oi = O[7 - k].y;
                const float tr =  fmaf(ct[k], orr, -st[k] * oi);
                const float ti = -fmaf(ct[k], oi,   st[k] * orr);
                Fs[n1][k][c] = mk(E[7 - k].x + tr, -E[7 - k].y + ti);
            }
        }
    }
    asm volatile("cp.async.wait_group 0;\n");
    __syncthreads();

    // ---- Stage B: fwd DIT-14 + weight mul + inv DIF-14, in-place pairs ----
    {
        const float ct[7] = CT14_TAB;
        const float st[7] = ST14_TAB;
        const int c  = tid & (CT_TILE - 1);
        const int k2 = tid / CT_TILE;   // 0..7

        float2 E[7], O[7];
        {
            float2 ve[7];
#pragma unroll
            for (int n = 0; n < 7; n++) ve[n] = Fs[2 * n][k2][c];
            cdft7<-1>(ve, E);
#pragma unroll
            for (int n = 0; n < 7; n++) ve[n] = Fs[2 * n + 1][k2][c];
            cdft7<-1>(ve, O);
        }

#pragma unroll
        for (int k = 0; k < 7; k++) {
            float Tr, Ti;
            if (k == 0) { Tr = O[0].x; Ti = O[0].y; }
            else {
                Tr = fmaf(ct[k], O[k].x,  st[k] * O[k].y);
                Ti = fmaf(ct[k], O[k].y, -st[k] * O[k].x);
            }
            const float Gr = E[k].x + Tr, Gi = E[k].y + Ti;   // G[k]
            const float Hr = E[k].x - Tr, Hi = E[k].y - Ti;   // G[k+7]
            const float2 wa = Ws[k][k2][c];
            const float2 wb = Ws[k + 7][k2][c];
            const float gr = fmaf(Gr, wa.x, -Gi * wa.y);
            const float gi = fmaf(Gr, wa.y,  Gi * wa.x);
            const float hr = fmaf(Hr, wb.x, -Hi * wb.y);
            const float hi = fmaf(Hr, wb.y,  Hi * wb.x);
            // DIF fold: p = g+h (even outputs), q = (g-h) e^{+2pi i k/14} (odd)
            E[k] = mk(gr + hr, gi + hi);
            const float dr = gr - hr, di = gi - hi;
            if (k == 0) O[0] = mk(dr, di);
            else O[k] = mk(fmaf(ct[k], dr, -st[k] * di),
                           fmaf(ct[k], di,  st[k] * dr));
        }

        float2* base = &Fs[0][k2][c];
        const int rowF2 = HALF_W * CTP;              // float2 stride per n
        cdft7_store<1>(E, base,          2 * rowF2); // even n = 2m
        cdft7_store<1>(O, base + rowF2,  2 * rowF2); // odd  n = 2m+1
    }
    __syncthreads();

    // ------- Stage C: c2r-14 over k2, float2 channel pairs -------
    if (tid < 14 * (CT_TILE / 2)) {
        const float c7[7] = C7_TAB;
        const float s7[7] = S7_TAB;
        const float ct[7] = CT14_TAB;
        const float st[7] = ST14_TAB;
        const int cp = tid & (CT_TILE / 2 - 1);
        const int n1 = tid / (CT_TILE / 2);

        float2 o[14];
#pragma unroll
        for (int h = 0; h < 2; h++) {
            const int c = 2 * cp + h;
            float2 V[HALF_W];
#pragma unroll
            for (int k = 0; k < HALF_W; k++) V[k] = Fs[n1][k][c];

            const float a0s = (V[0].x + V[7].x) * (1.0f / 196.0f);
            const float b0s = (V[0].x - V[7].x) * (1.0f / 196.0f);
            float2 a[4], bb[4];
#pragma unroll
            for (int k = 1; k <= 3; k++) {
                a[k] = mk(V[k].x + V[7 - k].x, V[k].y - V[7 - k].y);
                const float dr = V[k].x - V[7 - k].x;
                const float di = V[k].y + V[7 - k].y;
                bb[k] = mk(fmaf(ct[k], dr, -st[k] * di),
                           fmaf(ct[k], di,  st[k] * dr));
            }

#pragma unroll
            for (int m = 0; m < 7; m++) {
                float evn = a0s, odd = b0s;
#pragma unroll
                for (int k = 1; k <= 3; k++) {
                    const int j = (k * m) % 7;
                    evn = fmaf(a[k].x,   c7[j] * (2.0f / 196.0f), evn);
                    evn = fmaf(a[k].y,  -s7[j] * (2.0f / 196.0f), evn);
                    odd = fmaf(bb[k].x,  c7[j] * (2.0f / 196.0f), odd);
                    odd = fmaf(bb[k].y, -s7[j] * (2.0f / 196.0f), odd);
                }
                if (h) { o[2 * m].y = evn; o[2 * m + 1].y = odd; }
                else   { o[2 * m].x = evn; o[2 * m + 1].x = odd; }
            }
        }

        float2* orow =
            reinterpret_cast<float2*>(out + ((size_t)(b * 196 + n1 * 14)) * NCH + c0) + cp;
#pragma unroll
        for (int n = 0; n < 14; n++) orow[n * (NCH / 2)] = o[n];
    }
}

extern "C" void kernel_launch(void* const* d_in, const int* in_sizes, int n_in,
                              void* d_out, int out_size)
{
    const float* x  = (const float*)d_in[0];
    const float* cw = (const float*)d_in[1];
    float* out = (float*)d_out;
    (void)in_sizes; (void)n_in; (void)out_size;

    dim3 grid(NBATCH, NCH / CT_TILE);
    gf_kernel<<<grid, NTHREADS>>>(x, cw, out);
}

// round 7
// speedup vs baseline: 1.2080x; 1.2080x over previous
#include <cuda_runtime.h>

// GlobalFilter: out = irfft2( rfft2(x, ortho) * W, ortho ) per (batch, channel)
// x: [512, 196, 384] f32 ; W: [14, 8, 384, 2] f32 ; out: [512, 196, 384] f32
//
// Round 6: full channel-SIMD2 rewrite using Blackwell packed f32x2 FFMA2
// (PTX fma.rn.f32x2). Each thread processes a PAIR of channels packed in
// 64-bit registers; smem holds separate re/im float planes so an LDS.64 of
// a channel pair is a packed operand. 64-thread CTAs, Stage B = 8 k2 x 8
// channel-pairs. Weight cp.async staging of round 5 reverted (regressed).

#define NBATCH 512
#define HALF_W 8
#define NCH    384
#define CT_TILE 16
#define NPAIR  (CT_TILE / 2)      // 8 channel pairs per CTA
#define CTP    18                 // padded channel dim (floats, keeps pairs 8B-aligned)
#define RS     (HALF_W * CTP)     // floats per n-row in Fr/Fi
#define NTHREADS 64

#define C7_TAB {1.0f, 0.6234898018587336f, -0.2225209339563144f, -0.9009688679024191f, \
                -0.9009688679024191f, -0.2225209339563144f, 0.6234898018587336f}
#define S7_TAB {0.0f, 0.7818314824680298f, 0.9749279121818236f, 0.4338837391175581f, \
                -0.4338837391175581f, -0.9749279121818236f, -0.7818314824680298f}
#define CT14_TAB {1.0f, 0.9009688679024191f, 0.6234898018587336f, 0.2225209339563144f, \
                  -0.2225209339563144f, -0.6234898018587336f, -0.9009688679024191f}
#define ST14_TAB {0.0f, 0.4338837391175581f, 0.7818314824680298f, 0.9749279121818236f, \
                  0.9749279121818236f, 0.7818314824680298f, 0.4338837391175581f}

typedef unsigned long long u64;
struct FX2 { u64 v; };

__device__ __forceinline__ FX2 fpk(float lo, float hi) {
    FX2 r; asm("mov.b64 %0,{%1,%2};" : "=l"(r.v) : "f"(lo), "f"(hi)); return r;
}
__device__ __forceinline__ FX2 fpk2(float2 f) { return fpk(f.x, f.y); }
__device__ __forceinline__ float2 fup(FX2 a) {
    float2 f; asm("mov.b64 {%0,%1},%2;" : "=f"(f.x), "=f"(f.y) : "l"(a.v)); return f;
}
__device__ __forceinline__ FX2 fbc(float c) { return fpk(c, c); }
__device__ __forceinline__ FX2 fadd2(FX2 a, FX2 b) {
    FX2 r; asm("add.rn.f32x2 %0,%1,%2;" : "=l"(r.v) : "l"(a.v), "l"(b.v)); return r;
}
__device__ __forceinline__ FX2 fmul2(FX2 a, FX2 b) {
    FX2 r; asm("mul.rn.f32x2 %0,%1,%2;" : "=l"(r.v) : "l"(a.v), "l"(b.v)); return r;
}
__device__ __forceinline__ FX2 ffma2(FX2 a, FX2 b, FX2 c) {   // a*b + c
    FX2 r; asm("fma.rn.f32x2 %0,%1,%2,%3;" : "=l"(r.v) : "l"(a.v), "l"(b.v), "l"(c.v)); return r;
}
__device__ __forceinline__ FX2 fsub2(FX2 a, FX2 b) {          // a - b (exact)
    return ffma2(b, fbc(-1.0f), a);
}
__device__ __forceinline__ FX2 fscl(FX2 a, float c)  { return fmul2(a, fbc(c)); }
__device__ __forceinline__ FX2 fsfma(FX2 a, float c, FX2 acc) { return ffma2(a, fbc(c), acc); }

// Packed real DFT-7: bins 0..3 (bin 0 purely real).
__device__ __forceinline__ void rdft7p(const FX2 r[7], FX2& R0, FX2 Rr[4], FX2 Ri[4]) {
    const float c7[7] = C7_TAB;
    const float s7[7] = S7_TAB;
    FX2 tp[4], tm[4];
#pragma unroll
    for (int n = 1; n <= 3; n++) { tp[n] = fadd2(r[n], r[7 - n]); tm[n] = fsub2(r[n], r[7 - n]); }
    R0 = fadd2(fadd2(r[0], tp[1]), fadd2(tp[2], tp[3]));
#pragma unroll
    for (int k = 1; k <= 3; k++) {
        FX2 re = r[0], im = fscl(tm[1], -s7[k % 7]);
        re = fsfma(tp[1], c7[k % 7], re);
#pragma unroll
        for (int n = 2; n <= 3; n++) {
            const int j = (k * n) % 7;
            re = fsfma(tp[n], c7[j], re);
            im = fsfma(tm[n], -s7[j], im);
        }
        Rr[k] = re; Ri[k] = im;
    }
}

// Packed symmetric complex DFT-7. SGN=-1: e^{-2pi i kn/7}; +1: e^{+}.
template<int SGN>
__device__ __forceinline__ void cdft7p(const FX2 vr[7], const FX2 vi[7], FX2 Xr[7], FX2 Xi[7]) {
    const float c7[7] = C7_TAB;
    const float s7[7] = S7_TAB;
    FX2 tpr[4], tpi[4], tmr[4], tmi[4];
#pragma unroll
    for (int n = 1; n <= 3; n++) {
        tpr[n] = fadd2(vr[n], vr[7 - n]); tmr[n] = fsub2(vr[n], vr[7 - n]);
        tpi[n] = fadd2(vi[n], vi[7 - n]); tmi[n] = fsub2(vi[n], vi[7 - n]);
    }
    Xr[0] = fadd2(fadd2(vr[0], tpr[1]), fadd2(tpr[2], tpr[3]));
    Xi[0] = fadd2(fadd2(vi[0], tpi[1]), fadd2(tpi[2], tpi[3]));
#pragma unroll
    for (int k = 1; k <= 3; k++) {
        FX2 Ar = vr[0], Ai = vi[0];
        FX2 Br = fscl(tmr[1], s7[k % 7]), Bi = fscl(tmi[1], s7[k % 7]);
        Ar = fsfma(tpr[1], c7[k % 7], Ar);
        Ai = fsfma(tpi[1], c7[k % 7], Ai);
#pragma unroll
        for (int n = 2; n <= 3; n++) {
            const int j = (k * n) % 7;
            Ar = fsfma(tpr[n], c7[j], Ar);
            Ai = fsfma(tpi[n], c7[j], Ai);
            Br = fsfma(tmr[n], s7[j], Br);
            Bi = fsfma(tmi[n], s7[j], Bi);
        }
        if (SGN < 0) {
            Xr[k] = fadd2(Ar, Bi); Xi[k] = fsub2(Ai, Br);
            Xr[7 - k] = fsub2(Ar, Bi); Xi[7 - k] = fadd2(Ai, Br);
        } else {
            Xr[k] = fsub2(Ar, Bi); Xi[k] = fadd2(Ai, Br);
            Xr[7 - k] = fadd2(Ar, Bi); Xi[7 - k] = fsub2(Ai, Br);
        }
    }
}

// Packed inverse DFT-7 (e^{+}) storing straight to re/im smem planes.
// X[m] is written at fr/fi + m*strideF (floats), as a float2 channel pair.
__device__ __forceinline__ void cdft7p_store(const FX2 vr[7], const FX2 vi[7],
                                             float* fr, float* fi, const int strideF) {
    const float c7[7] = C7_TAB;
    const float s7[7] = S7_TAB;
    FX2 tpr[4], tpi[4], tmr[4], tmi[4];
#pragma unroll
    for (int n = 1; n <= 3; n++) {
        tpr[n] = fadd2(vr[n], vr[7 - n]); tmr[n] = fsub2(vr[n], vr[7 - n]);
        tpi[n] = fadd2(vi[n], vi[7 - n]); tmi[n] = fsub2(vi[n], vi[7 - n]);
    }
    *(float2*)fr = fup(fadd2(fadd2(vr[0], tpr[1]), fadd2(tpr[2], tpr[3])));
    *(float2*)fi = fup(fadd2(fadd2(vi[0], tpi[1]), fadd2(tpi[2], tpi[3])));
#pragma unroll
    for (int k = 1; k <= 3; k++) {
        FX2 Ar = vr[0], Ai = vi[0];
        FX2 Br = fscl(tmr[1], s7[k % 7]), Bi = fscl(tmi[1], s7[k % 7]);
        Ar = fsfma(tpr[1], c7[k % 7], Ar);
        Ai = fsfma(tpi[1], c7[k % 7], Ai);
#pragma unroll
        for (int n = 2; n <= 3; n++) {
            const int j = (k * n) % 7;
            Ar = fsfma(tpr[n], c7[j], Ar);
            Ai = fsfma(tpi[n], c7[j], Ai);
            Br = fsfma(tmr[n], s7[j], Br);
            Bi = fsfma(tmi[n], s7[j], Bi);
        }
        *(float2*)(fr + k * strideF)       = fup(fsub2(Ar, Bi));
        *(float2*)(fi + k * strideF)       = fup(fadd2(Ai, Br));
        *(float2*)(fr + (7 - k) * strideF) = fup(fadd2(Ar, Bi));
        *(float2*)(fi + (7 - k) * strideF) = fup(fsub2(Ai, Br));
    }
}

__global__ __launch_bounds__(NTHREADS, 10)
void gf_kernel(const float* __restrict__ x,
               const float* __restrict__ cw,
               float* __restrict__ out)
{
    __shared__ __align__(16) float Fr[14 * RS];   // re plane, ~8.1 KB
    __shared__ __align__(16) float Fi[14 * RS];   // im plane

    const int b   = blockIdx.x;
    const int c0  = blockIdx.y * CT_TILE;
    const int tid = threadIdx.x;

    // ---------- Stage A: row rfft-14 over n2, SIMD2 channel pairs ----------
    {
        const float ct[7] = CT14_TAB;
        const float st[7] = ST14_TAB;
        for (int t = tid; t < 14 * NPAIR; t += NTHREADS) {
            const int cp = t & (NPAIR - 1);
            const int n1 = t / NPAIR;
            const float2* xrow =
                reinterpret_cast<const float2*>(x + ((size_t)(b * 196 + n1 * 14)) * NCH + c0) + cp;
            FX2 in[14];
#pragma unroll
            for (int n = 0; n < 14; n++) in[n] = fpk2(xrow[n * (NCH / 2)]);

            FX2 ev[7], od[7];
#pragma unroll
            for (int n = 0; n < 7; n++) { ev[n] = in[2 * n]; od[n] = in[2 * n + 1]; }
            FX2 E0, O0, Er[4], Ei[4], Or[4], Oi[4];
            rdft7p(ev, E0, Er, Ei);
            rdft7p(od, O0, Or, Oi);

            float* fr = &Fr[n1 * RS + 2 * cp];
            float* fi = &Fi[n1 * RS + 2 * cp];
            *(float2*)(fr)              = fup(fadd2(E0, O0));
            *(float2*)(fi)              = make_float2(0.0f, 0.0f);
            *(float2*)(fr + 7 * CTP)    = fup(fsub2(E0, O0));
            *(float2*)(fi + 7 * CTP)    = make_float2(0.0f, 0.0f);
#pragma unroll
            for (int k = 1; k <= 3; k++) {   // F[k] = E[k] + (c - i s) O[k]
                FX2 tr = fsfma(Oi[k],  st[k], fscl(Or[k], ct[k]));
                FX2 ti = fsfma(Or[k], -st[k], fscl(Oi[k], ct[k]));
                *(float2*)(fr + k * CTP) = fup(fadd2(Er[k], tr));
                *(float2*)(fi + k * CTP) = fup(fadd2(Ei[k], ti));
            }
#pragma unroll
            for (int k = 4; k <= 6; k++) {   // conj-symmetry: E'[k]=conj(E[7-k])
                const int j = 7 - k;
                FX2 tr = fsfma(Oi[j], -st[k], fscl(Or[j], ct[k]));
                FX2 s  = fsfma(Or[j],  st[k], fscl(Oi[j], ct[k]));   // ct*Oi + st*Or
                *(float2*)(fr + k * CTP) = fup(fadd2(Er[j], tr));
                *(float2*)(fi + k * CTP) = fup(fscl(fadd2(Ei[j], s), -1.0f)); // -(Ei + s)
            }
        }
    }
    __syncthreads();

    // ---- Stage B: fwd DIT-14 + weight mul + inv DIF-14, SIMD2 pairs ----
    {
        const float ct[7] = CT14_TAB;
        const float st[7] = ST14_TAB;
        const int cp = tid & (NPAIR - 1);
        const int k2 = tid / NPAIR;   // 0..7

        float* frb = &Fr[k2 * CTP + 2 * cp];
        float* fib = &Fi[k2 * CTP + 2 * cp];

        FX2 Er[7], Ei[7], Or[7], Oi[7];
        {
            FX2 vr[7], vi[7];
#pragma unroll
            for (int n = 0; n < 7; n++) {
                vr[n] = fpk2(*(const float2*)(frb + (2 * n) * RS));
                vi[n] = fpk2(*(const float2*)(fib + (2 * n) * RS));
            }
            cdft7p<-1>(vr, vi, Er, Ei);
#pragma unroll
            for (int n = 0; n < 7; n++) {
                vr[n] = fpk2(*(const float2*)(frb + (2 * n + 1) * RS));
                vi[n] = fpk2(*(const float2*)(fib + (2 * n + 1) * RS));
            }
            cdft7p<-1>(vr, vi, Or, Oi);
        }

        // float4 weight load covers both channels of the pair: (wr0,wi0,wr1,wi1)
        const float4* wb4 = reinterpret_cast<const float4*>(cw)
                          + (((size_t)k2 * NCH) + c0 + 2 * cp) / 2;
        const int wstride = HALF_W * NCH / 2;   // float4 stride per k1
#pragma unroll
        for (int k = 0; k < 7; k++) {
            FX2 Tr, Ti;
            if (k == 0) { Tr = Or[0]; Ti = Oi[0]; }
            else {
                Tr = fsfma(Oi[k],  st[k], fscl(Or[k], ct[k]));
                Ti = fsfma(Or[k], -st[k], fscl(Oi[k], ct[k]));
            }
            const FX2 Gr = fadd2(Er[k], Tr), Gi = fadd2(Ei[k], Ti);   // G[k]
            const FX2 Hr = fsub2(Er[k], Tr), Hi = fsub2(Ei[k], Ti);   // G[k+7]
            const float4 wa = wb4[(size_t)k * wstride];
            const float4 wbv = wb4[(size_t)(k + 7) * wstride];
            const FX2 war = fpk(wa.x, wa.z),  wai = fpk(wa.y, wa.w);
            const FX2 wbr = fpk(wbv.x, wbv.z), wbi = fpk(wbv.y, wbv.w);
            const FX2 gr = fsub2(fmul2(Gr, war), fmul2(Gi, wai));
            const FX2 gi = ffma2(Gr, wai, fmul2(Gi, war));
            const FX2 hr = fsub2(fmul2(Hr, wbr), fmul2(Hi, wbi));
            const FX2 hi = ffma2(Hr, wbi, fmul2(Hi, wbr));
            // DIF fold: p = g+h (even outputs), q = (g-h) e^{+2pi i k/14} (odd)
            Er[k] = fadd2(gr, hr); Ei[k] = fadd2(gi, hi);
            const FX2 dr = fsub2(gr, hr), di = fsub2(gi, hi);
            if (k == 0) { Or[0] = dr; Oi[0] = di; }
            else {
                Or[k] = fsfma(di, -st[k], fscl(dr, ct[k]));
                Oi[k] = fsfma(dr,  st[k], fscl(di, ct[k]));
            }
        }

        // U[2m] = IDFT7(p), U[2m+1] = IDFT7(q), stored straight to smem
        cdft7p_store(Er, Ei, frb,      fib,      2 * RS);  // even n rows
        cdft7p_store(Or, Oi, frb + RS, fib + RS, 2 * RS);  // odd n rows
    }
    __syncthreads();

    // ---------- Stage C: c2r-14 over k2, SIMD2 channel pairs ----------
    {
        const float c7[7] = C7_TAB;
        const float s7[7] = S7_TAB;
        const float ct[7] = CT14_TAB;
        const float st[7] = ST14_TAB;
        for (int t = tid; t < 14 * NPAIR; t += NTHREADS) {
            const int cp = t & (NPAIR - 1);
            const int n1 = t / NPAIR;
            const float* frb = &Fr[n1 * RS + 2 * cp];
            const float* fib = &Fi[n1 * RS + 2 * cp];

            FX2 Vr[HALF_W], Vi[HALF_W];
#pragma unroll
            for (int k = 0; k < HALF_W; k++) {
                Vr[k] = fpk2(*(const float2*)(frb + k * CTP));
                Vi[k] = fpk2(*(const float2*)(fib + k * CTP));
            }

            const FX2 a0 = fscl(fadd2(Vr[0], Vr[7]), 1.0f / 196.0f);
            const FX2 b0 = fscl(fsub2(Vr[0], Vr[7]), 1.0f / 196.0f);
            FX2 ar[4], ai[4], br[4], bi[4];
#pragma unroll
            for (int k = 1; k <= 3; k++) {
                ar[k] = fadd2(Vr[k], Vr[7 - k]);
                ai[k] = fsub2(Vi[k], Vi[7 - k]);
                const FX2 dr = fsub2(Vr[k], Vr[7 - k]);
                const FX2 di = fadd2(Vi[k], Vi[7 - k]);
                br[k] = fsfma(di, -st[k], fscl(dr, ct[k]));
                bi[k] = fsfma(dr,  st[k], fscl(di, ct[k]));
            }

            float* orow = out + ((size_t)(b * 196 + n1 * 14)) * NCH + c0 + 2 * cp;
#pragma unroll
            for (int m = 0; m < 7; m++) {
                FX2 evn = a0, odd = b0;
#pragma unroll
                for (int k = 1; k <= 3; k++) {
                    const int j = (k * m) % 7;
                    evn = fsfma(ar[k],  c7[j] * (2.0f / 196.0f), evn);
                    evn = fsfma(ai[k], -s7[j] * (2.0f / 196.0f), evn);
                    odd = fsfma(br[k],  c7[j] * (2.0f / 196.0f), odd);
                    odd = fsfma(bi[k], -s7[j] * (2.0f / 196.0f), odd);
                }
                *(float2*)(orow + (size_t)(2 * m) * NCH)     = fup(evn);
                *(float2*)(orow + (size_t)(2 * m + 1) * NCH) = fup(odd);
            }
        }
    }
}

extern "C" void kernel_launch(void* const* d_in, const int* in_sizes, int n_in,
                              void* d_out, int out_size)
{
    const float* x  = (const float*)d_in[0];
    const float* cw = (const float*)d_in[1];
    float* out = (float*)d_out;
    (void)in_sizes; (void)n_in; (void)out_size;

    dim3 grid(NBATCH, NCH / CT_TILE);
    gf_kernel<<<grid, NTHREADS>>>(x, cw, out);
}